// round 15
// baseline (speedup 1.0000x reference)
#include <cuda_runtime.h>
#include <cuda_bf16.h>
#include <cstdint>
#include <math.h>

// ---------------- problem constants ----------------
#define BATCH   2
#define NTOK    5760
#define M_TOT   (BATCH * NTOK)   // 11520 tokens
#define DD      512              // model dim
#define HDIM    1960             // hidden dim
#define KTAPS   49               // 7x7
#define KH      7
#define CCH     40               // fold channels
#define HH      60
#define WWID    108
#define PAD     3
#define HP      66
#define WP      114
#define OHN     20
#define OWN     36
#define LLP     720
#define BPF     16
#define IMGPIX  (HP * WP)        // 7524
#define NIMG    (BPF * CCH)      // 640

// hi/lo two-plane layout: row = [hi(0:Kp) | lo(0:Kp)], stride 2*Kp
#define KP1     512              // GEMM1 K (exact)
#define KP2     2048             // GEMM2 K: 1960 padded to 64*32 (split-K=4 friendly)
#define KSPL4   512              // GEMM2 split-K quarter (16 stages)
#define NPAD1   2048             // 1960 padded to 16*128
#define NPAD2   512

// ---------------- scratch (static device globals; no allocations) ----------------
__device__ __nv_bfloat16 g_Aexp[(size_t)M_TOT * 2 * KP2];    // 94.4 MB (both GEMMs)
__device__ __nv_bfloat16 g_Bexp1[(size_t)NPAD1 * 2 * KP1];   // 4.2 MB
__device__ __nv_bfloat16 g_Bexp2[(size_t)NPAD2 * 2 * KP2];   // 4.2 MB
__device__ float g_h[(size_t)M_TOT * HDIM];                  // 90 MB
__device__ float g_img[(size_t)NIMG * IMGPIX];               // 19 MB
__device__ float g_part[(size_t)4 * M_TOT * DD];             // 94.4 MB (split-K partials)

// ============================================================================
// helpers
// ============================================================================
__device__ __forceinline__ uint32_t smem_to_u32(const void* p) {
    uint32_t a;
    asm("{ .reg .u64 t; cvta.to.shared.u64 t, %1; cvt.u32.u64 %0, t; }" : "=r"(a) : "l"(p));
    return a;
}
__device__ __forceinline__ void cp16(uint32_t s, const void* g) {
    asm volatile("cp.async.cg.shared.global [%0], [%1], 16;" :: "r"(s), "l"(g));
}
#define CP_COMMIT() asm volatile("cp.async.commit_group;" ::: "memory")
#define CP_WAIT0()  asm volatile("cp.async.wait_group 0;" ::: "memory")

__device__ __forceinline__ void ldm_x4(uint32_t& r0, uint32_t& r1, uint32_t& r2, uint32_t& r3,
                                       uint32_t addr) {
    asm volatile("ldmatrix.sync.aligned.m8n8.x4.shared.b16 {%0,%1,%2,%3}, [%4];"
                 : "=r"(r0), "=r"(r1), "=r"(r2), "=r"(r3) : "r"(addr));
}
__device__ __forceinline__ void mma_16816(float& c0, float& c1, float& c2, float& c3,
                                          uint32_t a0, uint32_t a1, uint32_t a2, uint32_t a3,
                                          uint32_t b0, uint32_t b1) {
    asm volatile("mma.sync.aligned.m16n8k16.row.col.f32.bf16.bf16.f32 "
                 "{%0,%1,%2,%3}, {%4,%5,%6,%7}, {%8,%9}, {%0,%1,%2,%3};"
                 : "+f"(c0), "+f"(c1), "+f"(c2), "+f"(c3)
                 : "r"(a0), "r"(a1), "r"(a2), "r"(a3), "r"(b0), "r"(b1));
}

// ============================================================================
// HMMA split-fp32 GEMM (PROVEN R11 BODY): C = A*B^T (+bias), hi/lo two-plane bf16.
// Per K-chunk accumulates hi*hi + hi*lo + lo*hi (fragments reused in regs).
// Split-K inside ONE launch: blockIdx.z selects K-window and partial plane.
// 128x128 CTA tile, BK=32, 256 threads (8 warps: 2m x 4n, 64x32 warp tiles).
// 2-stage cp.async pipeline (80 KB smem -> 2 CTAs/SM), one sync per stage.
// ============================================================================
#define ROWB   80u               // padded row bytes (64B data + 16B pad)
#define HTILE  (128u * ROWB)     // 10240 B (one half-tile per stage)
#define STG_B  (4u * HTILE)      // 40960 B per stage (Ahi|Alo|Bhi|Blo)
#define STAGES 2
#define GEMM_SMEM (STAGES * STG_B)   // 81920 B -> 2 CTAs/SM

__global__ __launch_bounds__(256, 2)
void hmma_gemm(const __nv_bfloat16* __restrict__ A, const __nv_bfloat16* __restrict__ B,
               const float* __restrict__ bias, float* __restrict__ C,
               int Kp, int kLen, int N)
{
    extern __shared__ __align__(16) char smem[];
    const uint32_t sbase = smem_to_u32(smem);
    const int strideK = 2 * Kp;
    const int kOff = blockIdx.z * kLen;
    C += (size_t)blockIdx.z * (size_t)(gridDim.y * 128) * N;   // partial plane per z

    const int tid  = threadIdx.x;
    const int wid  = tid >> 5;
    const int lane = tid & 31;
    const int row0 = blockIdx.y * 128;
    const int col0 = blockIdx.x * 128;

    const int wm = wid & 1;       // m offset wm*64
    const int wn = wid >> 1;      // n offset wn*32

    // loader mapping: 256 threads cover 64 rows x 4 chunks of 16B per pass
    const int lrow = tid >> 2;    // 0..63
    const int lch  = tid & 3;     // 16B chunk in 64B row
    const __nv_bfloat16* Ag = A + (size_t)(row0 + lrow) * strideK + kOff + lch * 8;
    const __nv_bfloat16* Bg = B + (size_t)(col0 + lrow) * strideK + kOff + lch * 8;

    float acc[4][4][4];
#pragma unroll
    for (int mi = 0; mi < 4; mi++)
#pragma unroll
        for (int ni = 0; ni < 4; ni++)
#pragma unroll
            for (int r = 0; r < 4; r++) acc[mi][ni][r] = 0.f;

    const int nk = kLen >> 5;     // BK=32 stages

    // ---- prologue: issue stage 0 ----
    {
        const uint32_t sb = sbase;
#pragma unroll
        for (int rr = 0; rr < 128; rr += 64) {
            const uint32_t so = (lrow + rr) * ROWB + lch * 16;
            cp16(sb + 0 * HTILE + so, Ag + rr * (size_t)strideK);
            cp16(sb + 1 * HTILE + so, Ag + rr * (size_t)strideK + Kp);
            cp16(sb + 2 * HTILE + so, Bg + rr * (size_t)strideK);
            cp16(sb + 3 * HTILE + so, Bg + rr * (size_t)strideK + Kp);
        }
        CP_COMMIT();
    }

    // fragment-load lane maps
    const uint32_t aOff = (uint32_t)((wm * 64 + (lane & 15)) * ROWB + ((lane >> 4) << 4));
    const uint32_t bOff = (uint32_t)((wn * 32 + (lane & 7) + ((lane >> 4) << 3)) * ROWB
                                     + (((lane >> 3) & 1) << 4));

    for (int i = 0; i < nk; i++) {
        CP_WAIT0();               // stage i arrived (this thread's parts)
        __syncthreads();          // all parts visible; previous compute done by all

        if (i + 1 < nk) {         // issue stage i+1 into the other buffer
            const uint32_t sb = sbase + ((i + 1) & 1) * STG_B;
            const int k0 = (i + 1) << 5;
#pragma unroll
            for (int rr = 0; rr < 128; rr += 64) {
                const uint32_t so = (lrow + rr) * ROWB + lch * 16;
                cp16(sb + 0 * HTILE + so, Ag + rr * (size_t)strideK + k0);
                cp16(sb + 1 * HTILE + so, Ag + rr * (size_t)strideK + k0 + Kp);
                cp16(sb + 2 * HTILE + so, Bg + rr * (size_t)strideK + k0);
                cp16(sb + 3 * HTILE + so, Bg + rr * (size_t)strideK + k0 + Kp);
            }
            CP_COMMIT();
        }

        const uint32_t sb = sbase + (i & 1) * STG_B;
        const uint32_t aHi = sb + 0 * HTILE + aOff;
        const uint32_t aLo = sb + 1 * HTILE + aOff;
        const uint32_t bHi = sb + 2 * HTILE + bOff;
        const uint32_t bLo = sb + 3 * HTILE + bOff;

#pragma unroll
        for (int ks = 0; ks < 2; ks++) {
            const uint32_t kb = ks * 32;
            uint32_t afh[4][4], bfh[4][2], bfl[4][2];
            // A-hi fragments (4x ldmatrix.x4)
#pragma unroll
            for (int mi = 0; mi < 4; mi++)
                ldm_x4(afh[mi][0], afh[mi][1], afh[mi][2], afh[mi][3],
                       aHi + (uint32_t)(mi * 16 * ROWB) + kb);
            // B-hi + B-lo fragments (2x ldmatrix.x4 each: 2 n-blocks per op)
#pragma unroll
            for (int p = 0; p < 2; p++) {
                ldm_x4(bfh[2*p][0], bfh[2*p][1], bfh[2*p+1][0], bfh[2*p+1][1],
                       bHi + (uint32_t)(p * 16 * ROWB) + kb);
                ldm_x4(bfl[2*p][0], bfl[2*p][1], bfl[2*p+1][0], bfl[2*p+1][1],
                       bLo + (uint32_t)(p * 16 * ROWB) + kb);
            }
            // hi * hi
#pragma unroll
            for (int mi = 0; mi < 4; mi++)
#pragma unroll
                for (int ni = 0; ni < 4; ni++)
                    mma_16816(acc[mi][ni][0], acc[mi][ni][1], acc[mi][ni][2], acc[mi][ni][3],
                              afh[mi][0], afh[mi][1], afh[mi][2], afh[mi][3],
                              bfh[ni][0], bfh[ni][1]);
            // A-lo fragments (latency hidden by hi*hi MMAs above)
            uint32_t afl[4][4];
#pragma unroll
            for (int mi = 0; mi < 4; mi++)
                ldm_x4(afl[mi][0], afl[mi][1], afl[mi][2], afl[mi][3],
                       aLo + (uint32_t)(mi * 16 * ROWB) + kb);
            // hi * lo
#pragma unroll
            for (int mi = 0; mi < 4; mi++)
#pragma unroll
                for (int ni = 0; ni < 4; ni++)
                    mma_16816(acc[mi][ni][0], acc[mi][ni][1], acc[mi][ni][2], acc[mi][ni][3],
                              afh[mi][0], afh[mi][1], afh[mi][2], afh[mi][3],
                              bfl[ni][0], bfl[ni][1]);
            // lo * hi
#pragma unroll
            for (int mi = 0; mi < 4; mi++)
#pragma unroll
                for (int ni = 0; ni < 4; ni++)
                    mma_16816(acc[mi][ni][0], acc[mi][ni][1], acc[mi][ni][2], acc[mi][ni][3],
                              afl[mi][0], afl[mi][1], afl[mi][2], afl[mi][3],
                              bfh[ni][0], bfh[ni][1]);
        }
    }

    // ---- epilogue ----
    const int g = lane >> 2, t = lane & 3;
#pragma unroll
    for (int mi = 0; mi < 4; mi++) {
        const int row = row0 + wm * 64 + mi * 16 + g;
#pragma unroll
        for (int ni = 0; ni < 4; ni++) {
            const int col = col0 + wn * 32 + ni * 8 + 2 * t;
            if (col < N) {
                float bc0 = 0.f, bc1 = 0.f;
                if (bias) { bc0 = bias[col]; bc1 = bias[col + 1]; }
                float2 v0 = make_float2(acc[mi][ni][0] + bc0, acc[mi][ni][1] + bc1);
                float2 v1 = make_float2(acc[mi][ni][2] + bc0, acc[mi][ni][3] + bc1);
                *reinterpret_cast<float2*>(&C[(size_t)row * N + col]) = v0;
                *reinterpret_cast<float2*>(&C[(size_t)(row + 8) * N + col]) = v1;
            }
        }
    }
}

// ---------------- split-K=4 reduction: out = p0+p1+p2+p3 + bias ----------------
__global__ void reduce4_bias_kernel(const float* __restrict__ part,
                                    const float* __restrict__ bias, float* __restrict__ out)
{
    const int idx = blockIdx.x * blockDim.x + threadIdx.x;    // float4 units
    if (idx >= M_TOT * DD / 4) return;
    const int col4 = (idx % (DD / 4)) * 4;
    const size_t plane = (size_t)M_TOT * DD / 4;              // in float4 units
    const float4 a = reinterpret_cast<const float4*>(part)[idx];
    const float4 b = reinterpret_cast<const float4*>(part)[idx + plane];
    const float4 c = reinterpret_cast<const float4*>(part)[idx + 2 * plane];
    const float4 d = reinterpret_cast<const float4*>(part)[idx + 3 * plane];
    const float4 bs = *reinterpret_cast<const float4*>(&bias[col4]);
    float4 v;
    v.x = (a.x + b.x) + (c.x + d.x) + bs.x;
    v.y = (a.y + b.y) + (c.y + d.y) + bs.y;
    v.z = (a.z + b.z) + (c.z + d.z) + bs.z;
    v.w = (a.w + b.w) + (c.w + d.w) + bs.w;
    reinterpret_cast<float4*>(out)[idx] = v;
}

// ============================================================================
// bf16 split helpers + expansion kernels
// ============================================================================
__device__ __forceinline__ void split_bf16(float v, __nv_bfloat16& hi, __nv_bfloat16& lo) {
    hi = __float2bfloat16(v);
    lo = __float2bfloat16(v - __bfloat162float(hi));
}
__device__ __forceinline__ uint32_t pack_bf162(__nv_bfloat16 a, __nv_bfloat16 b) {
    __nv_bfloat162 p; p.x = a; p.y = b;
    return *reinterpret_cast<uint32_t*>(&p);
}

// x (M_TOT x 512 fp32) -> Aexp rows [hi(0:512) | lo(0:512)], 4 elems/thread, 8B stores
__global__ void expand_x_kernel(const float* __restrict__ x, __nv_bfloat16* __restrict__ Aexp)
{
    const int idx = blockIdx.x * blockDim.x + threadIdx.x;     // quads
    if (idx >= M_TOT * (KP1 / 4)) return;
    const int m = idx / (KP1 / 4), kq = idx % (KP1 / 4);
    const int k = kq * 4;
    const float4 v = *reinterpret_cast<const float4*>(&x[(size_t)m * DD + k]);
    __nv_bfloat16 h0, l0, h1, l1, h2, l2, h3, l3;
    split_bf16(v.x, h0, l0); split_bf16(v.y, h1, l1);
    split_bf16(v.z, h2, l2); split_bf16(v.w, h3, l3);
    uint2 hp, lp;
    hp.x = pack_bf162(h0, h1); hp.y = pack_bf162(h2, h3);
    lp.x = pack_bf162(l0, l1); lp.y = pack_bf162(l2, l3);
    const size_t base = (size_t)m * (2 * KP1) + k;
    *reinterpret_cast<uint2*>(&Aexp[base])       = hp;
    *reinterpret_cast<uint2*>(&Aexp[base + KP1]) = lp;
}

// W (K x N fp32, row-major) -> Bexp rows [hi(0:Kp) | lo(0:Kp)], n-guarded, k-padded
__global__ void expand_W_kernel(const float* __restrict__ W, __nv_bfloat16* __restrict__ Bexp,
                                int K, int Kp, int N, int Npad)
{
    const int idx = blockIdx.x * blockDim.x + threadIdx.x;
    if (idx >= Npad * 2 * Kp) return;
    const int n = idx / (2 * Kp), col = idx % (2 * Kp);
    const int plane = col >= Kp;
    const int k = col - plane * Kp;
    __nv_bfloat16 outv = __float2bfloat16(0.f);
    if (n < N && k < K) {
        __nv_bfloat16 hi, lo;
        split_bf16(W[(size_t)k * N + n], hi, lo);
        outv = plane ? lo : hi;
    }
    Bexp[idx] = outv;
}

// ---------------- fold (gather) + normalize + crop/zero-pad ----------------
__global__ void fold_kernel(const float* __restrict__ h, float* __restrict__ img)
{
    const int idx = blockIdx.x * blockDim.x + threadIdx.x;
    if (idx >= BPF * (CCH / 4) * IMGPIX) return;
    const int pix = idx % IMGPIX;
    const int rest = idx / IMGPIX;
    const int cg  = rest % (CCH / 4);    // 0..9
    const int bp  = rest / (CCH / 4);
    const int pi  = pix / WP;
    const int pj  = pix % WP;

    float out[4] = {0.f, 0.f, 0.f, 0.f};
    if (pi >= PAD && pi < PAD + HH && pj >= PAD && pj < PAD + WWID) {
        const int oi_lo = max(0, (pi - 4) / 3);
        const int oi_hi = min(OHN - 1, pi / 3);
        const int oj_lo = max(0, (pj - 4) / 3);
        const int oj_hi = min(OWN - 1, pj / 3);
        float sum[4] = {0.f, 0.f, 0.f, 0.f};
        for (int oi = oi_lo; oi <= oi_hi; ++oi) {
            const int ki = pi - 3 * oi;
            for (int oj = oj_lo; oj <= oj_hi; ++oj) {
                const int kj = pj - 3 * oj;
                const size_t base = (size_t)(bp * LLP + oi * OWN + oj) * HDIM
                                  + cg * KTAPS + ki * KH + kj;
#pragma unroll
                for (int t = 0; t < 4; t++)
                    sum[t] += h[base + t * (10 * KTAPS)];
            }
        }
        const float inv = 1.f / (float)((oi_hi - oi_lo + 1) * (oj_hi - oj_lo + 1));
#pragma unroll
        for (int t = 0; t < 4; t++) out[t] = sum[t] * inv;
    }
#pragma unroll
    for (int t = 0; t < 4; t++)
        img[(size_t)(bp * CCH + cg + 10 * t) * IMGPIX + pix] = out[t];
}

// ---------------- unfold + exact GELU + hi/lo split (4 j's/thread, 8B stores) ----
// Writes Aexp rows [hi(0:2048) | lo(0:2048)], stride 4096; zeroes K padding [1960,2048).
__global__ void unfold_gelu_expand_kernel(const float* __restrict__ img,
                                          __nv_bfloat16* __restrict__ Aexp)
{
    const int idx = blockIdx.x * blockDim.x + threadIdx.x;     // quads over HDIM
    if (idx >= M_TOT * (HDIM / 4)) return;
    const int jq    = idx % (HDIM / 4);
    const int token = idx / (HDIM / 4);
    const int j  = jq * 4;
    const int bp = token / LLP;
    const int l  = token % LLP;
    const int oi = l / OWN, oj = l % OWN;
    const int base_pix = (oi * 3) * WP + (oj * 3);
    const float* img_bp = img + (size_t)bp * CCH * IMGPIX + base_pix;

    __nv_bfloat16 hh[4], ll[4];
#pragma unroll
    for (int u = 0; u < 4; u++) {
        const int jj = j + u;
        const int c  = jj / KTAPS;
        const int k  = jj - c * KTAPS;
        const int ki = k / KH, kj = k - ki * KH;
        const float v = img_bp[(size_t)c * IMGPIX + ki * WP + kj];
        const float ge = 0.5f * v * (1.f + erff(v * 0.7071067811865475f));
        split_bf16(ge, hh[u], ll[u]);
    }
    uint2 hp, lp;
    hp.x = pack_bf162(hh[0], hh[1]); hp.y = pack_bf162(hh[2], hh[3]);
    lp.x = pack_bf162(ll[0], ll[1]); lp.y = pack_bf162(ll[2], ll[3]);
    const size_t base = (size_t)token * (2 * KP2) + j;
    *reinterpret_cast<uint2*>(&Aexp[base])       = hp;
    *reinterpret_cast<uint2*>(&Aexp[base + KP2]) = lp;

    // last quad of each token row also zeroes the K padding [1960,2048), both planes
    if (j == HDIM - 4) {
        const uint2 z = make_uint2(0u, 0u);
        const size_t rb = (size_t)token * (2 * KP2);
#pragma unroll
        for (int p = 0; p < (KP2 - HDIM) / 4; p++) {          // 22 quads
            *reinterpret_cast<uint2*>(&Aexp[rb + HDIM + p * 4])       = z;
            *reinterpret_cast<uint2*>(&Aexp[rb + KP2 + HDIM + p * 4]) = z;
        }
    }
}

// ---------------- launch ----------------
extern "C" void kernel_launch(void* const* d_in, const int* in_sizes, int n_in,
                              void* d_out, int out_size)
{
    const float* x  = (const float*)d_in[0];   // (2, 5760, 512)
    const float* W1 = (const float*)d_in[1];   // (512, 1960)
    const float* b1 = (const float*)d_in[2];   // (1960,)
    const float* W2 = (const float*)d_in[3];   // (1960, 512)
    const float* b2 = (const float*)d_in[4];   // (512,)
    float* out = (float*)d_out;                // (2, 5760, 512)

    __nv_bfloat16 *Aexp, *Bexp1, *Bexp2;
    float *h_ptr, *img_ptr, *part;
    cudaGetSymbolAddress((void**)&Aexp,    g_Aexp);
    cudaGetSymbolAddress((void**)&Bexp1,   g_Bexp1);
    cudaGetSymbolAddress((void**)&Bexp2,   g_Bexp2);
    cudaGetSymbolAddress((void**)&h_ptr,   g_h);
    cudaGetSymbolAddress((void**)&img_ptr, g_img);
    cudaGetSymbolAddress((void**)&part,    g_part);

    cudaFuncSetAttribute(hmma_gemm, cudaFuncAttributeMaxDynamicSharedMemorySize, GEMM_SMEM);

    // 1) expand x -> Aexp (hi/lo, stride 1024)
    {
        int n = M_TOT * (KP1 / 4);
        expand_x_kernel<<<(n + 255) / 256, 256>>>(x, Aexp);
    }
    // 2) expand W1 -> Bexp1
    {
        int nb = NPAD1 * 2 * KP1;
        expand_W_kernel<<<(nb + 255) / 256, 256>>>(W1, Bexp1, DD, KP1, HDIM, NPAD1);
    }
    // 3) expand W2 -> Bexp2
    {
        int nb = NPAD2 * 2 * KP2;
        expand_W_kernel<<<(nb + 255) / 256, 256>>>(W2, Bexp2, HDIM, KP2, DD, NPAD2);
    }
    // 4) GEMM1: h = x @ W1 + b1
    {
        dim3 grid(NPAD1 / 128, M_TOT / 128, 1);   // (16, 90)
        hmma_gemm<<<grid, 256, GEMM_SMEM>>>(Aexp, Bexp1, b1, h_ptr, KP1, KP1, HDIM);
    }
    // 5) fold + normalize
    {
        const int total = BPF * (CCH / 4) * IMGPIX;
        fold_kernel<<<(total + 255) / 256, 256>>>(h_ptr, img_ptr);
    }
    // 6) unfold + gelu + hi/lo split (Aexp reused; zeroes its own K padding)
    {
        const int total = M_TOT * (HDIM / 4);
        unfold_gelu_expand_kernel<<<(total + 255) / 256, 256>>>(img_ptr, Aexp);
    }
    // 7) GEMM2 split-K=4 in ONE launch (1440 CTAs -> ~97% wave eff), then reduce+bias
    {
        dim3 grid(NPAD2 / 128, M_TOT / 128, 4);   // (4, 90, 4) = 1440 CTAs
        hmma_gemm<<<grid, 256, GEMM_SMEM>>>(Aexp, Bexp2, nullptr, part, KP2, KSPL4, DD);
        const int total = M_TOT * DD / 4;
        reduce4_bias_kernel<<<(total + 255) / 256, 256>>>(part, b2, out);
    }
}

// round 16
// speedup vs baseline: 1.0038x; 1.0038x over previous
#include <cuda_runtime.h>
#include <cuda_bf16.h>
#include <cstdint>
#include <math.h>

// ---------------- problem constants ----------------
#define BATCH   2
#define NTOK    5760
#define M_TOT   (BATCH * NTOK)   // 11520 tokens
#define DD      512              // model dim
#define HDIM    1960             // hidden dim
#define KTAPS   49               // 7x7
#define KH      7
#define CCH     40               // fold channels
#define HH      60
#define WWID    108
#define PAD     3
#define HP      66
#define WP      114
#define OHN     20
#define OWN     36
#define LLP     720
#define BPF     16
#define IMGPIX  (HP * WP)        // 7524
#define NIMG    (BPF * CCH)      // 640

// hi/lo two-plane layout: row = [hi(0:Kp) | lo(0:Kp)], stride 2*Kp
#define KP1     512              // GEMM1 K (exact)
#define KP2     1984             // GEMM2 K: 1960 padded to 62*32
#define KSPLIT  992              // GEMM2 split-K half (31 stages)
#define NPAD1   2048             // 1960 padded to 16*128
#define NPAD2   512

// ---------------- scratch (static device globals; no allocations) ----------------
__device__ __nv_bfloat16 g_Aexp[(size_t)M_TOT * 2 * KP2];    // 91.4 MB (both GEMMs)
__device__ __nv_bfloat16 g_Bexp1[(size_t)NPAD1 * 2 * KP1];   // 4.2 MB
__device__ __nv_bfloat16 g_Bexp2[(size_t)NPAD2 * 2 * KP2];   // 4.1 MB
__device__ float g_h[(size_t)M_TOT * HDIM];                  // 90 MB (reused: GEMM2 split-K partials)
__device__ float g_img[(size_t)NIMG * IMGPIX];               // 19 MB

// ============================================================================
// helpers
// ============================================================================
__device__ __forceinline__ uint32_t smem_to_u32(const void* p) {
    uint32_t a;
    asm("{ .reg .u64 t; cvta.to.shared.u64 t, %1; cvt.u32.u64 %0, t; }" : "=r"(a) : "l"(p));
    return a;
}
__device__ __forceinline__ void cp16(uint32_t s, const void* g) {
    asm volatile("cp.async.cg.shared.global [%0], [%1], 16;" :: "r"(s), "l"(g));
}
#define CP_COMMIT() asm volatile("cp.async.commit_group;" ::: "memory")
#define CP_WAIT0()  asm volatile("cp.async.wait_group 0;" ::: "memory")

__device__ __forceinline__ void ldm_x4(uint32_t& r0, uint32_t& r1, uint32_t& r2, uint32_t& r3,
                                       uint32_t addr) {
    asm volatile("ldmatrix.sync.aligned.m8n8.x4.shared.b16 {%0,%1,%2,%3}, [%4];"
                 : "=r"(r0), "=r"(r1), "=r"(r2), "=r"(r3) : "r"(addr));
}
__device__ __forceinline__ void mma_16816(float& c0, float& c1, float& c2, float& c3,
                                          uint32_t a0, uint32_t a1, uint32_t a2, uint32_t a3,
                                          uint32_t b0, uint32_t b1) {
    asm volatile("mma.sync.aligned.m16n8k16.row.col.f32.bf16.bf16.f32 "
                 "{%0,%1,%2,%3}, {%4,%5,%6,%7}, {%8,%9}, {%0,%1,%2,%3};"
                 : "+f"(c0), "+f"(c1), "+f"(c2), "+f"(c3)
                 : "r"(a0), "r"(a1), "r"(a2), "r"(a3), "r"(b0), "r"(b1));
}

// ============================================================================
// HMMA split-fp32 GEMM (PROVEN R11 BODY): C = A*B^T (+bias), hi/lo two-plane bf16.
// Per K-chunk accumulates hi*hi + hi*lo + lo*hi (fragments reused in regs).
// Split-K inside ONE launch: blockIdx.z selects K-window and partial plane.
// 128x128 CTA tile, BK=32, 256 threads (8 warps: 2m x 4n, 64x32 warp tiles).
// 2-stage cp.async pipeline (80 KB smem -> 2 CTAs/SM), one sync per stage.
// ============================================================================
#define ROWB   80u               // padded row bytes (64B data + 16B pad)
#define HTILE  (128u * ROWB)     // 10240 B (one half-tile per stage)
#define STG_B  (4u * HTILE)      // 40960 B per stage (Ahi|Alo|Bhi|Blo)
#define STAGES 2
#define GEMM_SMEM (STAGES * STG_B)   // 81920 B -> 2 CTAs/SM

__global__ __launch_bounds__(256, 2)
void hmma_gemm(const __nv_bfloat16* __restrict__ A, const __nv_bfloat16* __restrict__ B,
               const float* __restrict__ bias, float* __restrict__ C,
               int Kp, int kLen, int N)
{
    extern __shared__ __align__(16) char smem[];
    const uint32_t sbase = smem_to_u32(smem);
    const int strideK = 2 * Kp;
    const int kOff = blockIdx.z * kLen;
    C += (size_t)blockIdx.z * (size_t)(gridDim.y * 128) * N;   // partial plane per z

    const int tid  = threadIdx.x;
    const int wid  = tid >> 5;
    const int lane = tid & 31;
    const int row0 = blockIdx.y * 128;
    const int col0 = blockIdx.x * 128;

    const int wm = wid & 1;       // m offset wm*64
    const int wn = wid >> 1;      // n offset wn*32

    // loader mapping: 256 threads cover 64 rows x 4 chunks of 16B per pass
    const int lrow = tid >> 2;    // 0..63
    const int lch  = tid & 3;     // 16B chunk in 64B row
    const __nv_bfloat16* Ag = A + (size_t)(row0 + lrow) * strideK + kOff + lch * 8;
    const __nv_bfloat16* Bg = B + (size_t)(col0 + lrow) * strideK + kOff + lch * 8;

    float acc[4][4][4];
#pragma unroll
    for (int mi = 0; mi < 4; mi++)
#pragma unroll
        for (int ni = 0; ni < 4; ni++)
#pragma unroll
            for (int r = 0; r < 4; r++) acc[mi][ni][r] = 0.f;

    const int nk = kLen >> 5;     // BK=32 stages

    // ---- prologue: issue stage 0 ----
    {
        const uint32_t sb = sbase;
#pragma unroll
        for (int rr = 0; rr < 128; rr += 64) {
            const uint32_t so = (lrow + rr) * ROWB + lch * 16;
            cp16(sb + 0 * HTILE + so, Ag + rr * (size_t)strideK);
            cp16(sb + 1 * HTILE + so, Ag + rr * (size_t)strideK + Kp);
            cp16(sb + 2 * HTILE + so, Bg + rr * (size_t)strideK);
            cp16(sb + 3 * HTILE + so, Bg + rr * (size_t)strideK + Kp);
        }
        CP_COMMIT();
    }

    // fragment-load lane maps
    const uint32_t aOff = (uint32_t)((wm * 64 + (lane & 15)) * ROWB + ((lane >> 4) << 4));
    const uint32_t bOff = (uint32_t)((wn * 32 + (lane & 7) + ((lane >> 4) << 3)) * ROWB
                                     + (((lane >> 3) & 1) << 4));

    for (int i = 0; i < nk; i++) {
        CP_WAIT0();               // stage i arrived (this thread's parts)
        __syncthreads();          // all parts visible; previous compute done by all

        if (i + 1 < nk) {         // issue stage i+1 into the other buffer
            const uint32_t sb = sbase + ((i + 1) & 1) * STG_B;
            const int k0 = (i + 1) << 5;
#pragma unroll
            for (int rr = 0; rr < 128; rr += 64) {
                const uint32_t so = (lrow + rr) * ROWB + lch * 16;
                cp16(sb + 0 * HTILE + so, Ag + rr * (size_t)strideK + k0);
                cp16(sb + 1 * HTILE + so, Ag + rr * (size_t)strideK + k0 + Kp);
                cp16(sb + 2 * HTILE + so, Bg + rr * (size_t)strideK + k0);
                cp16(sb + 3 * HTILE + so, Bg + rr * (size_t)strideK + k0 + Kp);
            }
            CP_COMMIT();
        }

        const uint32_t sb = sbase + (i & 1) * STG_B;
        const uint32_t aHi = sb + 0 * HTILE + aOff;
        const uint32_t aLo = sb + 1 * HTILE + aOff;
        const uint32_t bHi = sb + 2 * HTILE + bOff;
        const uint32_t bLo = sb + 3 * HTILE + bOff;

#pragma unroll
        for (int ks = 0; ks < 2; ks++) {
            const uint32_t kb = ks * 32;
            uint32_t afh[4][4], bfh[4][2], bfl[4][2];
            // A-hi fragments (4x ldmatrix.x4)
#pragma unroll
            for (int mi = 0; mi < 4; mi++)
                ldm_x4(afh[mi][0], afh[mi][1], afh[mi][2], afh[mi][3],
                       aHi + (uint32_t)(mi * 16 * ROWB) + kb);
            // B-hi + B-lo fragments (2x ldmatrix.x4 each: 2 n-blocks per op)
#pragma unroll
            for (int p = 0; p < 2; p++) {
                ldm_x4(bfh[2*p][0], bfh[2*p][1], bfh[2*p+1][0], bfh[2*p+1][1],
                       bHi + (uint32_t)(p * 16 * ROWB) + kb);
                ldm_x4(bfl[2*p][0], bfl[2*p][1], bfl[2*p+1][0], bfl[2*p+1][1],
                       bLo + (uint32_t)(p * 16 * ROWB) + kb);
            }
            // hi * hi
#pragma unroll
            for (int mi = 0; mi < 4; mi++)
#pragma unroll
                for (int ni = 0; ni < 4; ni++)
                    mma_16816(acc[mi][ni][0], acc[mi][ni][1], acc[mi][ni][2], acc[mi][ni][3],
                              afh[mi][0], afh[mi][1], afh[mi][2], afh[mi][3],
                              bfh[ni][0], bfh[ni][1]);
            // A-lo fragments (latency hidden by hi*hi MMAs above)
            uint32_t afl[4][4];
#pragma unroll
            for (int mi = 0; mi < 4; mi++)
                ldm_x4(afl[mi][0], afl[mi][1], afl[mi][2], afl[mi][3],
                       aLo + (uint32_t)(mi * 16 * ROWB) + kb);
            // hi * lo
#pragma unroll
            for (int mi = 0; mi < 4; mi++)
#pragma unroll
                for (int ni = 0; ni < 4; ni++)
                    mma_16816(acc[mi][ni][0], acc[mi][ni][1], acc[mi][ni][2], acc[mi][ni][3],
                              afh[mi][0], afh[mi][1], afh[mi][2], afh[mi][3],
                              bfl[ni][0], bfl[ni][1]);
            // lo * hi
#pragma unroll
            for (int mi = 0; mi < 4; mi++)
#pragma unroll
                for (int ni = 0; ni < 4; ni++)
                    mma_16816(acc[mi][ni][0], acc[mi][ni][1], acc[mi][ni][2], acc[mi][ni][3],
                              afl[mi][0], afl[mi][1], afl[mi][2], afl[mi][3],
                              bfh[ni][0], bfh[ni][1]);
        }
    }

    // ---- epilogue ----
    const int g = lane >> 2, t = lane & 3;
#pragma unroll
    for (int mi = 0; mi < 4; mi++) {
        const int row = row0 + wm * 64 + mi * 16 + g;
#pragma unroll
        for (int ni = 0; ni < 4; ni++) {
            const int col = col0 + wn * 32 + ni * 8 + 2 * t;
            if (col < N) {
                float bc0 = 0.f, bc1 = 0.f;
                if (bias) { bc0 = bias[col]; bc1 = bias[col + 1]; }
                float2 v0 = make_float2(acc[mi][ni][0] + bc0, acc[mi][ni][1] + bc1);
                float2 v1 = make_float2(acc[mi][ni][2] + bc0, acc[mi][ni][3] + bc1);
                *reinterpret_cast<float2*>(&C[(size_t)row * N + col]) = v0;
                *reinterpret_cast<float2*>(&C[(size_t)(row + 8) * N + col]) = v1;
            }
        }
    }
}

// ---------------- split-K reduction: out = p0 + p1 + bias ----------------
__global__ void reduce_bias_kernel(const float* __restrict__ p0, const float* __restrict__ p1,
                                   const float* __restrict__ bias, float* __restrict__ out)
{
    const int idx = blockIdx.x * blockDim.x + threadIdx.x;    // float4 units
    if (idx >= M_TOT * DD / 4) return;
    const int col4 = (idx % (DD / 4)) * 4;
    const float4 a = reinterpret_cast<const float4*>(p0)[idx];
    const float4 b = reinterpret_cast<const float4*>(p1)[idx];
    const float4 bs = *reinterpret_cast<const float4*>(&bias[col4]);
    float4 v;
    v.x = a.x + b.x + bs.x;
    v.y = a.y + b.y + bs.y;
    v.z = a.z + b.z + bs.z;
    v.w = a.w + b.w + bs.w;
    reinterpret_cast<float4*>(out)[idx] = v;
}

// ============================================================================
// bf16 split helpers + expansion kernels
// ============================================================================
__device__ __forceinline__ void split_bf16(float v, __nv_bfloat16& hi, __nv_bfloat16& lo) {
    hi = __float2bfloat16(v);
    lo = __float2bfloat16(v - __bfloat162float(hi));
}
__device__ __forceinline__ uint32_t pack_bf162(__nv_bfloat16 a, __nv_bfloat16 b) {
    __nv_bfloat162 p; p.x = a; p.y = b;
    return *reinterpret_cast<uint32_t*>(&p);
}

// x (M_TOT x 512 fp32) -> Aexp rows [hi(0:512) | lo(0:512)], 4 elems/thread, 8B stores
__global__ void expand_x_kernel(const float* __restrict__ x, __nv_bfloat16* __restrict__ Aexp)
{
    const int idx = blockIdx.x * blockDim.x + threadIdx.x;     // quads
    if (idx >= M_TOT * (KP1 / 4)) return;
    const int m = idx / (KP1 / 4), kq = idx % (KP1 / 4);
    const int k = kq * 4;
    const float4 v = *reinterpret_cast<const float4*>(&x[(size_t)m * DD + k]);
    __nv_bfloat16 h0, l0, h1, l1, h2, l2, h3, l3;
    split_bf16(v.x, h0, l0); split_bf16(v.y, h1, l1);
    split_bf16(v.z, h2, l2); split_bf16(v.w, h3, l3);
    uint2 hp, lp;
    hp.x = pack_bf162(h0, h1); hp.y = pack_bf162(h2, h3);
    lp.x = pack_bf162(l0, l1); lp.y = pack_bf162(l2, l3);
    const size_t base = (size_t)m * (2 * KP1) + k;
    *reinterpret_cast<uint2*>(&Aexp[base])       = hp;
    *reinterpret_cast<uint2*>(&Aexp[base + KP1]) = lp;
}

// W (K x N fp32, row-major) -> Bexp rows [hi(0:Kp) | lo(0:Kp)], n-guarded, k-padded
__global__ void expand_W_kernel(const float* __restrict__ W, __nv_bfloat16* __restrict__ Bexp,
                                int K, int Kp, int N, int Npad)
{
    const int idx = blockIdx.x * blockDim.x + threadIdx.x;
    if (idx >= Npad * 2 * Kp) return;
    const int n = idx / (2 * Kp), col = idx % (2 * Kp);
    const int plane = col >= Kp;
    const int k = col - plane * Kp;
    __nv_bfloat16 outv = __float2bfloat16(0.f);
    if (n < N && k < K) {
        __nv_bfloat16 hi, lo;
        split_bf16(W[(size_t)k * N + n], hi, lo);
        outv = plane ? lo : hi;
    }
    Bexp[idx] = outv;
}

// ---------------- fold (gather) + normalize + crop/zero-pad ----------------
// 8 channels per thread (c = cg + 5t, t<8): 8 independent loads per tap -> 2x MLP.
__global__ void fold_kernel(const float* __restrict__ h, float* __restrict__ img)
{
    const int idx = blockIdx.x * blockDim.x + threadIdx.x;
    if (idx >= BPF * (CCH / 8) * IMGPIX) return;
    const int pix = idx % IMGPIX;
    const int rest = idx / IMGPIX;
    const int cg  = rest % (CCH / 8);    // 0..4
    const int bp  = rest / (CCH / 8);
    const int pi  = pix / WP;
    const int pj  = pix % WP;

    float out[8] = {0.f, 0.f, 0.f, 0.f, 0.f, 0.f, 0.f, 0.f};
    if (pi >= PAD && pi < PAD + HH && pj >= PAD && pj < PAD + WWID) {
        const int oi_lo = max(0, (pi - 4) / 3);
        const int oi_hi = min(OHN - 1, pi / 3);
        const int oj_lo = max(0, (pj - 4) / 3);
        const int oj_hi = min(OWN - 1, pj / 3);
        float sum[8] = {0.f, 0.f, 0.f, 0.f, 0.f, 0.f, 0.f, 0.f};
        for (int oi = oi_lo; oi <= oi_hi; ++oi) {
            const int ki = pi - 3 * oi;
            for (int oj = oj_lo; oj <= oj_hi; ++oj) {
                const int kj = pj - 3 * oj;
                const size_t base = (size_t)(bp * LLP + oi * OWN + oj) * HDIM
                                  + cg * KTAPS + ki * KH + kj;
#pragma unroll
                for (int t = 0; t < 8; t++)
                    sum[t] += h[base + t * (5 * KTAPS)];
            }
        }
        const float inv = 1.f / (float)((oi_hi - oi_lo + 1) * (oj_hi - oj_lo + 1));
#pragma unroll
        for (int t = 0; t < 8; t++) out[t] = sum[t] * inv;
    }
#pragma unroll
    for (int t = 0; t < 8; t++)
        img[(size_t)(bp * CCH + cg + 5 * t) * IMGPIX + pix] = out[t];
}

// ---------------- unfold + exact GELU + hi/lo split (4 j's/thread, 8B stores) ----
// Writes Aexp rows [hi(0:1984) | lo(0:1984)], stride 3968; also zeroes K padding.
__global__ void unfold_gelu_expand_kernel(const float* __restrict__ img,
                                          __nv_bfloat16* __restrict__ Aexp)
{
    const int idx = blockIdx.x * blockDim.x + threadIdx.x;     // quads over HDIM
    if (idx >= M_TOT * (HDIM / 4)) return;
    const int jq    = idx % (HDIM / 4);
    const int token = idx / (HDIM / 4);
    const int j  = jq * 4;
    const int bp = token / LLP;
    const int l  = token % LLP;
    const int oi = l / OWN, oj = l % OWN;
    const int base_pix = (oi * 3) * WP + (oj * 3);
    const float* img_bp = img + (size_t)bp * CCH * IMGPIX + base_pix;

    __nv_bfloat16 hh[4], ll[4];
#pragma unroll
    for (int u = 0; u < 4; u++) {
        const int jj = j + u;
        const int c  = jj / KTAPS;
        const int k  = jj - c * KTAPS;
        const int ki = k / KH, kj = k - ki * KH;
        const float v = img_bp[(size_t)c * IMGPIX + ki * WP + kj];
        const float ge = 0.5f * v * (1.f + erff(v * 0.7071067811865475f));
        split_bf16(ge, hh[u], ll[u]);
    }
    uint2 hp, lp;
    hp.x = pack_bf162(hh[0], hh[1]); hp.y = pack_bf162(hh[2], hh[3]);
    lp.x = pack_bf162(ll[0], ll[1]); lp.y = pack_bf162(ll[2], ll[3]);
    const size_t base = (size_t)token * (2 * KP2) + j;
    *reinterpret_cast<uint2*>(&Aexp[base])       = hp;
    *reinterpret_cast<uint2*>(&Aexp[base + KP2]) = lp;

    // last quad of each token row also zeroes the K padding [1960,1984), both planes
    if (j == HDIM - 4) {
        const uint2 z = make_uint2(0u, 0u);
        const size_t rb = (size_t)token * (2 * KP2);
#pragma unroll
        for (int p = 0; p < (KP2 - HDIM) / 4; p++) {          // 6 quads
            *reinterpret_cast<uint2*>(&Aexp[rb + HDIM + p * 4])       = z;
            *reinterpret_cast<uint2*>(&Aexp[rb + KP2 + HDIM + p * 4]) = z;
        }
    }
}

// ---------------- launch ----------------
extern "C" void kernel_launch(void* const* d_in, const int* in_sizes, int n_in,
                              void* d_out, int out_size)
{
    const float* x  = (const float*)d_in[0];   // (2, 5760, 512)
    const float* W1 = (const float*)d_in[1];   // (512, 1960)
    const float* b1 = (const float*)d_in[2];   // (1960,)
    const float* W2 = (const float*)d_in[3];   // (1960, 512)
    const float* b2 = (const float*)d_in[4];   // (512,)
    float* out = (float*)d_out;                // (2, 5760, 512)

    __nv_bfloat16 *Aexp, *Bexp1, *Bexp2;
    float *h_ptr, *img_ptr;
    cudaGetSymbolAddress((void**)&Aexp,    g_Aexp);
    cudaGetSymbolAddress((void**)&Bexp1,   g_Bexp1);
    cudaGetSymbolAddress((void**)&Bexp2,   g_Bexp2);
    cudaGetSymbolAddress((void**)&h_ptr,   g_h);
    cudaGetSymbolAddress((void**)&img_ptr, g_img);

    cudaFuncSetAttribute(hmma_gemm, cudaFuncAttributeMaxDynamicSharedMemorySize, GEMM_SMEM);

    // 1) expand x -> Aexp (hi/lo, stride 1024)
    {
        int n = M_TOT * (KP1 / 4);
        expand_x_kernel<<<(n + 255) / 256, 256>>>(x, Aexp);
    }
    // 2) expand W1 -> Bexp1
    {
        int nb = NPAD1 * 2 * KP1;
        expand_W_kernel<<<(nb + 255) / 256, 256>>>(W1, Bexp1, DD, KP1, HDIM, NPAD1);
    }
    // 3) expand W2 -> Bexp2
    {
        int nb = NPAD2 * 2 * KP2;
        expand_W_kernel<<<(nb + 255) / 256, 256>>>(W2, Bexp2, HDIM, KP2, DD, NPAD2);
    }
    // 4) GEMM1: h = x @ W1 + b1
    {
        dim3 grid(NPAD1 / 128, M_TOT / 128, 1);   // (16, 90)
        hmma_gemm<<<grid, 256, GEMM_SMEM>>>(Aexp, Bexp1, b1, h_ptr, KP1, KP1, HDIM);
    }
    // 5) fold + normalize (8 channels/thread)
    {
        const int total = BPF * (CCH / 8) * IMGPIX;
        fold_kernel<<<(total + 255) / 256, 256>>>(h_ptr, img_ptr);
    }
    // 6) unfold + gelu + hi/lo split (Aexp reused; zeroes its own K padding)
    {
        const int total = M_TOT * (HDIM / 4);
        unfold_gelu_expand_kernel<<<(total + 255) / 256, 256>>>(img_ptr, Aexp);
    }
    // 7) GEMM2 split-K=2 in ONE launch (720 CTAs pack into 3 waves), then reduce+bias
    {
        float* p0 = h_ptr;                              // z=0 partial (22.5 MB)
        float* p1 = h_ptr + (size_t)M_TOT * DD;         // z=1 partial (22.5 MB)
        dim3 grid(NPAD2 / 128, M_TOT / 128, 2);         // (4, 90, 2) = 720 CTAs
        hmma_gemm<<<grid, 256, GEMM_SMEM>>>(Aexp, Bexp2, nullptr, p0, KP2, KSPLIT, DD);
        const int total = M_TOT * DD / 4;
        reduce_bias_kernel<<<(total + 255) / 256, 256>>>(p0, p1, b2, out);
    }
}

// round 17
// speedup vs baseline: 1.3595x; 1.3543x over previous
#include <cuda_runtime.h>
#include <cuda_fp16.h>
#include <cstdint>
#include <math.h>

// ---------------- problem constants ----------------
#define BATCH   2
#define NTOK    5760
#define M_TOT   (BATCH * NTOK)   // 11520 tokens
#define DD      512              // model dim
#define HDIM    1960             // hidden dim
#define KTAPS   49               // 7x7
#define KH      7
#define CCH     40               // fold channels
#define HH      60
#define WWID    108
#define PAD     3
#define HP      66
#define WP      114
#define OHN     20
#define OWN     36
#define LLP     720
#define BPF     16
#define IMGPIX  (HP * WP)        // 7524
#define NIMG    (BPF * CCH)      // 640

// A: single fp16 plane (rounded). B: fp16 hi/lo two planes [hi | lo], stride 2*Kp.
#define KP1     512              // GEMM1 K (exact)
#define KP2     1984             // GEMM2 K: 1960 padded to 62*32
#define KSPLIT  992              // GEMM2 split-K half (31 stages)
#define NPAD1   2048             // 1960 padded to 16*128
#define NPAD2   512

// ---------------- scratch (static device globals; no allocations) ----------------
__device__ __half g_Aexp[(size_t)M_TOT * KP2];               // 45.7 MB (both GEMMs)
__device__ __half g_Bexp1[(size_t)NPAD1 * 2 * KP1];          // 4.2 MB
__device__ __half g_Bexp2[(size_t)NPAD2 * 2 * KP2];          // 4.1 MB
__device__ float g_h[(size_t)M_TOT * HDIM];                  // 90 MB (reused: GEMM2 split-K partials)
__device__ float g_img[(size_t)NIMG * IMGPIX];               // 19 MB

// ============================================================================
// helpers
// ============================================================================
__device__ __forceinline__ uint32_t smem_to_u32(const void* p) {
    uint32_t a;
    asm("{ .reg .u64 t; cvta.to.shared.u64 t, %1; cvt.u32.u64 %0, t; }" : "=r"(a) : "l"(p));
    return a;
}
__device__ __forceinline__ void cp16(uint32_t s, const void* g) {
    asm volatile("cp.async.cg.shared.global [%0], [%1], 16;" :: "r"(s), "l"(g));
}
#define CP_COMMIT() asm volatile("cp.async.commit_group;" ::: "memory")
#define CP_WAIT0()  asm volatile("cp.async.wait_group 0;" ::: "memory")

__device__ __forceinline__ void ldm_x4(uint32_t& r0, uint32_t& r1, uint32_t& r2, uint32_t& r3,
                                       uint32_t addr) {
    asm volatile("ldmatrix.sync.aligned.m8n8.x4.shared.b16 {%0,%1,%2,%3}, [%4];"
                 : "=r"(r0), "=r"(r1), "=r"(r2), "=r"(r3) : "r"(addr));
}
__device__ __forceinline__ void mma_16816(float& c0, float& c1, float& c2, float& c3,
                                          uint32_t a0, uint32_t a1, uint32_t a2, uint32_t a3,
                                          uint32_t b0, uint32_t b1) {
    asm volatile("mma.sync.aligned.m16n8k16.row.col.f32.f16.f16.f32 "
                 "{%0,%1,%2,%3}, {%4,%5,%6,%7}, {%8,%9}, {%0,%1,%2,%3};"
                 : "+f"(c0), "+f"(c1), "+f"(c2), "+f"(c3)
                 : "r"(a0), "r"(a1), "r"(a2), "r"(a3), "r"(b0), "r"(b1));
}

// ============================================================================
// HMMA fp16-split GEMM: C = A*B^T (+bias).
// A: rounded fp16, single plane, row stride Kp. B: fp16 hi/lo planes, stride 2*Kp.
// Per K-chunk: C += A*Bhi + A*Blo  (2 MMA terms; A fragments reused).
// Split-K inside ONE launch: blockIdx.z selects K-window and partial plane.
// 128x128 CTA tile, BK=32, 256 threads (8 warps: 2m x 4n, 64x32 warp tiles).
// 2-stage cp.async pipeline (60 KB smem -> 2 CTAs/SM), one sync per stage.
// ============================================================================
#define ROWB   80u               // padded row bytes (64B data + 16B pad)
#define HTILE  (128u * ROWB)     // 10240 B (one half-tile per stage)
#define STG_B  (3u * HTILE)      // 30720 B per stage (A|Bhi|Blo)
#define STAGES 2
#define GEMM_SMEM (STAGES * STG_B)   // 61440 B -> 2 CTAs/SM

__global__ __launch_bounds__(256, 2)
void hmma_gemm(const __half* __restrict__ A, const __half* __restrict__ B,
               const float* __restrict__ bias, float* __restrict__ C,
               int Kp, int kLen, int N)
{
    extern __shared__ __align__(16) char smem[];
    const uint32_t sbase = smem_to_u32(smem);
    const int strideB = 2 * Kp;
    const int kOff = blockIdx.z * kLen;
    C += (size_t)blockIdx.z * (size_t)(gridDim.y * 128) * N;   // partial plane per z

    const int tid  = threadIdx.x;
    const int wid  = tid >> 5;
    const int lane = tid & 31;
    const int row0 = blockIdx.y * 128;
    const int col0 = blockIdx.x * 128;

    const int wm = wid & 1;       // m offset wm*64
    const int wn = wid >> 1;      // n offset wn*32

    // loader mapping: 256 threads cover 64 rows x 4 chunks of 16B per pass
    const int lrow = tid >> 2;    // 0..63
    const int lch  = tid & 3;     // 16B chunk in 64B row
    const __half* Ag = A + (size_t)(row0 + lrow) * Kp + kOff + lch * 8;
    const __half* Bg = B + (size_t)(col0 + lrow) * strideB + kOff + lch * 8;

    float acc[4][4][4];
#pragma unroll
    for (int mi = 0; mi < 4; mi++)
#pragma unroll
        for (int ni = 0; ni < 4; ni++)
#pragma unroll
            for (int r = 0; r < 4; r++) acc[mi][ni][r] = 0.f;

    const int nk = kLen >> 5;     // BK=32 stages

    // ---- prologue: issue stage 0 ----
    {
        const uint32_t sb = sbase;
#pragma unroll
        for (int rr = 0; rr < 128; rr += 64) {
            const uint32_t so = (lrow + rr) * ROWB + lch * 16;
            cp16(sb + 0 * HTILE + so, Ag + rr * (size_t)Kp);
            cp16(sb + 1 * HTILE + so, Bg + rr * (size_t)strideB);
            cp16(sb + 2 * HTILE + so, Bg + rr * (size_t)strideB + Kp);
        }
        CP_COMMIT();
    }

    // fragment-load lane maps
    const uint32_t aOff = (uint32_t)((wm * 64 + (lane & 15)) * ROWB + ((lane >> 4) << 4));
    const uint32_t bOff = (uint32_t)((wn * 32 + (lane & 7) + ((lane >> 4) << 3)) * ROWB
                                     + (((lane >> 3) & 1) << 4));

    for (int i = 0; i < nk; i++) {
        CP_WAIT0();               // stage i arrived (this thread's parts)
        __syncthreads();          // all parts visible; previous compute done by all

        if (i + 1 < nk) {         // issue stage i+1 into the other buffer
            const uint32_t sb = sbase + ((i + 1) & 1) * STG_B;
            const int k0 = (i + 1) << 5;
#pragma unroll
            for (int rr = 0; rr < 128; rr += 64) {
                const uint32_t so = (lrow + rr) * ROWB + lch * 16;
                cp16(sb + 0 * HTILE + so, Ag + rr * (size_t)Kp + k0);
                cp16(sb + 1 * HTILE + so, Bg + rr * (size_t)strideB + k0);
                cp16(sb + 2 * HTILE + so, Bg + rr * (size_t)strideB + k0 + Kp);
            }
            CP_COMMIT();
        }

        const uint32_t sb = sbase + (i & 1) * STG_B;
        const uint32_t aF  = sb + 0 * HTILE + aOff;
        const uint32_t bHi = sb + 1 * HTILE + bOff;
        const uint32_t bLo = sb + 2 * HTILE + bOff;

#pragma unroll
        for (int ks = 0; ks < 2; ks++) {
            const uint32_t kb = ks * 32;
            uint32_t af[4][4], bfh[4][2], bfl[4][2];
            // A fragments (4x ldmatrix.x4)
#pragma unroll
            for (int mi = 0; mi < 4; mi++)
                ldm_x4(af[mi][0], af[mi][1], af[mi][2], af[mi][3],
                       aF + (uint32_t)(mi * 16 * ROWB) + kb);
            // B-hi + B-lo fragments (2x ldmatrix.x4 each: 2 n-blocks per op)
#pragma unroll
            for (int p = 0; p < 2; p++) {
                ldm_x4(bfh[2*p][0], bfh[2*p][1], bfh[2*p+1][0], bfh[2*p+1][1],
                       bHi + (uint32_t)(p * 16 * ROWB) + kb);
                ldm_x4(bfl[2*p][0], bfl[2*p][1], bfl[2*p+1][0], bfl[2*p+1][1],
                       bLo + (uint32_t)(p * 16 * ROWB) + kb);
            }
            // A * B_hi
#pragma unroll
            for (int mi = 0; mi < 4; mi++)
#pragma unroll
                for (int ni = 0; ni < 4; ni++)
                    mma_16816(acc[mi][ni][0], acc[mi][ni][1], acc[mi][ni][2], acc[mi][ni][3],
                              af[mi][0], af[mi][1], af[mi][2], af[mi][3],
                              bfh[ni][0], bfh[ni][1]);
            // A * B_lo
#pragma unroll
            for (int mi = 0; mi < 4; mi++)
#pragma unroll
                for (int ni = 0; ni < 4; ni++)
                    mma_16816(acc[mi][ni][0], acc[mi][ni][1], acc[mi][ni][2], acc[mi][ni][3],
                              af[mi][0], af[mi][1], af[mi][2], af[mi][3],
                              bfl[ni][0], bfl[ni][1]);
        }
    }

    // ---- epilogue ----
    const int g = lane >> 2, t = lane & 3;
#pragma unroll
    for (int mi = 0; mi < 4; mi++) {
        const int row = row0 + wm * 64 + mi * 16 + g;
#pragma unroll
        for (int ni = 0; ni < 4; ni++) {
            const int col = col0 + wn * 32 + ni * 8 + 2 * t;
            if (col < N) {
                float bc0 = 0.f, bc1 = 0.f;
                if (bias) { bc0 = bias[col]; bc1 = bias[col + 1]; }
                float2 v0 = make_float2(acc[mi][ni][0] + bc0, acc[mi][ni][1] + bc1);
                float2 v1 = make_float2(acc[mi][ni][2] + bc0, acc[mi][ni][3] + bc1);
                *reinterpret_cast<float2*>(&C[(size_t)row * N + col]) = v0;
                *reinterpret_cast<float2*>(&C[(size_t)(row + 8) * N + col]) = v1;
            }
        }
    }
}

// ---------------- split-K reduction: out = p0 + p1 + bias ----------------
__global__ void reduce_bias_kernel(const float* __restrict__ p0, const float* __restrict__ p1,
                                   const float* __restrict__ bias, float* __restrict__ out)
{
    const int idx = blockIdx.x * blockDim.x + threadIdx.x;    // float4 units
    if (idx >= M_TOT * DD / 4) return;
    const int col4 = (idx % (DD / 4)) * 4;
    const float4 a = reinterpret_cast<const float4*>(p0)[idx];
    const float4 b = reinterpret_cast<const float4*>(p1)[idx];
    const float4 bs = *reinterpret_cast<const float4*>(&bias[col4]);
    float4 v;
    v.x = a.x + b.x + bs.x;
    v.y = a.y + b.y + bs.y;
    v.z = a.z + b.z + bs.z;
    v.w = a.w + b.w + bs.w;
    reinterpret_cast<float4*>(out)[idx] = v;
}

// ============================================================================
// fp16 split helpers + expansion kernels
// ============================================================================
__device__ __forceinline__ void split_fp16(float v, __half& hi, __half& lo) {
    hi = __float2half_rn(v);
    lo = __float2half_rn(v - __half2float(hi));
}
__device__ __forceinline__ uint32_t pack_h2(__half a, __half b) {
    __half2 p; p.x = a; p.y = b;
    return *reinterpret_cast<uint32_t*>(&p);
}

// x (M_TOT x 512 fp32) -> A plane fp16 (rounded), 4 elems/thread, 8B stores
__global__ void expand_x_kernel(const float* __restrict__ x, __half* __restrict__ Aexp)
{
    const int idx = blockIdx.x * blockDim.x + threadIdx.x;     // quads
    if (idx >= M_TOT * (KP1 / 4)) return;
    const int m = idx / (KP1 / 4), kq = idx % (KP1 / 4);
    const int k = kq * 4;
    const float4 v = *reinterpret_cast<const float4*>(&x[(size_t)m * DD + k]);
    uint2 hp;
    hp.x = pack_h2(__float2half_rn(v.x), __float2half_rn(v.y));
    hp.y = pack_h2(__float2half_rn(v.z), __float2half_rn(v.w));
    *reinterpret_cast<uint2*>(&Aexp[(size_t)m * KP1 + k]) = hp;
}

// W (K x N fp32, row-major) -> Bexp rows [hi(0:Kp) | lo(0:Kp)], n-guarded, k-padded
__global__ void expand_W_kernel(const float* __restrict__ W, __half* __restrict__ Bexp,
                                int K, int Kp, int N, int Npad)
{
    const int idx = blockIdx.x * blockDim.x + threadIdx.x;
    if (idx >= Npad * 2 * Kp) return;
    const int n = idx / (2 * Kp), col = idx % (2 * Kp);
    const int plane = col >= Kp;
    const int k = col - plane * Kp;
    __half outv = __float2half_rn(0.f);
    if (n < N && k < K) {
        __half hi, lo;
        split_fp16(W[(size_t)k * N + n], hi, lo);
        outv = plane ? lo : hi;
    }
    Bexp[idx] = outv;
}

// ---------------- fold (gather) + normalize + crop/zero-pad (R13 proven) ------
__global__ void fold_kernel(const float* __restrict__ h, float* __restrict__ img)
{
    const int idx = blockIdx.x * blockDim.x + threadIdx.x;
    if (idx >= BPF * (CCH / 4) * IMGPIX) return;
    const int pix = idx % IMGPIX;
    const int rest = idx / IMGPIX;
    const int cg  = rest % (CCH / 4);    // 0..9
    const int bp  = rest / (CCH / 4);
    const int pi  = pix / WP;
    const int pj  = pix % WP;

    float out[4] = {0.f, 0.f, 0.f, 0.f};
    if (pi >= PAD && pi < PAD + HH && pj >= PAD && pj < PAD + WWID) {
        const int oi_lo = max(0, (pi - 4) / 3);
        const int oi_hi = min(OHN - 1, pi / 3);
        const int oj_lo = max(0, (pj - 4) / 3);
        const int oj_hi = min(OWN - 1, pj / 3);
        float sum[4] = {0.f, 0.f, 0.f, 0.f};
        for (int oi = oi_lo; oi <= oi_hi; ++oi) {
            const int ki = pi - 3 * oi;
            for (int oj = oj_lo; oj <= oj_hi; ++oj) {
                const int kj = pj - 3 * oj;
                const size_t base = (size_t)(bp * LLP + oi * OWN + oj) * HDIM
                                  + cg * KTAPS + ki * KH + kj;
#pragma unroll
                for (int t = 0; t < 4; t++)
                    sum[t] += h[base + t * (10 * KTAPS)];
            }
        }
        const float inv = 1.f / (float)((oi_hi - oi_lo + 1) * (oj_hi - oj_lo + 1));
#pragma unroll
        for (int t = 0; t < 4; t++) out[t] = sum[t] * inv;
    }
#pragma unroll
    for (int t = 0; t < 4; t++)
        img[(size_t)(bp * CCH + cg + 10 * t) * IMGPIX + pix] = out[t];
}

// ---------------- unfold + exact GELU + fp16 round (4 j's/thread, 8B stores) ----
// Writes A plane (stride KP2); zeroes K padding [1960,1984).
__global__ void unfold_gelu_expand_kernel(const float* __restrict__ img,
                                          __half* __restrict__ Aexp)
{
    const int idx = blockIdx.x * blockDim.x + threadIdx.x;     // quads over HDIM
    if (idx >= M_TOT * (HDIM / 4)) return;
    const int jq    = idx % (HDIM / 4);
    const int token = idx / (HDIM / 4);
    const int j  = jq * 4;
    const int bp = token / LLP;
    const int l  = token % LLP;
    const int oi = l / OWN, oj = l % OWN;
    const int base_pix = (oi * 3) * WP + (oj * 3);
    const float* img_bp = img + (size_t)bp * CCH * IMGPIX + base_pix;

    __half hh[4];
#pragma unroll
    for (int u = 0; u < 4; u++) {
        const int jj = j + u;
        const int c  = jj / KTAPS;
        const int k  = jj - c * KTAPS;
        const int ki = k / KH, kj = k - ki * KH;
        const float v = img_bp[(size_t)c * IMGPIX + ki * WP + kj];
        const float ge = 0.5f * v * (1.f + erff(v * 0.7071067811865475f));
        hh[u] = __float2half_rn(ge);
    }
    uint2 hp;
    hp.x = pack_h2(hh[0], hh[1]);
    hp.y = pack_h2(hh[2], hh[3]);
    *reinterpret_cast<uint2*>(&Aexp[(size_t)token * KP2 + j]) = hp;

    // last quad of each token row also zeroes the K padding [1960,1984)
    if (j == HDIM - 4) {
        const uint2 z = make_uint2(0u, 0u);
        const size_t rb = (size_t)token * KP2;
#pragma unroll
        for (int p = 0; p < (KP2 - HDIM) / 4; p++)            // 6 quads
            *reinterpret_cast<uint2*>(&Aexp[rb + HDIM + p * 4]) = z;
    }
}

// ---------------- launch ----------------
extern "C" void kernel_launch(void* const* d_in, const int* in_sizes, int n_in,
                              void* d_out, int out_size)
{
    const float* x  = (const float*)d_in[0];   // (2, 5760, 512)
    const float* W1 = (const float*)d_in[1];   // (512, 1960)
    const float* b1 = (const float*)d_in[2];   // (1960,)
    const float* W2 = (const float*)d_in[3];   // (1960, 512)
    const float* b2 = (const float*)d_in[4];   // (512,)
    float* out = (float*)d_out;                // (2, 5760, 512)

    __half *Aexp, *Bexp1, *Bexp2;
    float *h_ptr, *img_ptr;
    cudaGetSymbolAddress((void**)&Aexp,    g_Aexp);
    cudaGetSymbolAddress((void**)&Bexp1,   g_Bexp1);
    cudaGetSymbolAddress((void**)&Bexp2,   g_Bexp2);
    cudaGetSymbolAddress((void**)&h_ptr,   g_h);
    cudaGetSymbolAddress((void**)&img_ptr, g_img);

    cudaFuncSetAttribute(hmma_gemm, cudaFuncAttributeMaxDynamicSharedMemorySize, GEMM_SMEM);

    // 1) expand x -> A plane (fp16 rounded, stride 512)
    {
        int n = M_TOT * (KP1 / 4);
        expand_x_kernel<<<(n + 255) / 256, 256>>>(x, Aexp);
    }
    // 2) expand W1 -> Bexp1 (hi/lo)
    {
        int nb = NPAD1 * 2 * KP1;
        expand_W_kernel<<<(nb + 255) / 256, 256>>>(W1, Bexp1, DD, KP1, HDIM, NPAD1);
    }
    // 3) expand W2 -> Bexp2 (hi/lo)
    {
        int nb = NPAD2 * 2 * KP2;
        expand_W_kernel<<<(nb + 255) / 256, 256>>>(W2, Bexp2, HDIM, KP2, DD, NPAD2);
    }
    // 4) GEMM1: h = x @ W1 + b1
    {
        dim3 grid(NPAD1 / 128, M_TOT / 128, 1);   // (16, 90)
        hmma_gemm<<<grid, 256, GEMM_SMEM>>>(Aexp, Bexp1, b1, h_ptr, KP1, KP1, HDIM);
    }
    // 5) fold + normalize (4 channels/thread, R13 proven)
    {
        const int total = BPF * (CCH / 4) * IMGPIX;
        fold_kernel<<<(total + 255) / 256, 256>>>(h_ptr, img_ptr);
    }
    // 6) unfold + gelu + fp16 round (A plane reused, stride 1984; zeroes own pad)
    {
        const int total = M_TOT * (HDIM / 4);
        unfold_gelu_expand_kernel<<<(total + 255) / 256, 256>>>(img_ptr, Aexp);
    }
    // 7) GEMM2 split-K=2 in ONE launch, then reduce+bias
    {
        float* p0 = h_ptr;                              // z=0 partial (22.5 MB)
        float* p1 = h_ptr + (size_t)M_TOT * DD;         // z=1 partial (22.5 MB)
        dim3 grid(NPAD2 / 128, M_TOT / 128, 2);         // (4, 90, 2) = 720 CTAs
        hmma_gemm<<<grid, 256, GEMM_SMEM>>>(Aexp, Bexp2, nullptr, p0, KP2, KSPLIT, DD);
        const int total = M_TOT * DD / 4;
        reduce_bias_kernel<<<(total + 255) / 256, 256>>>(p0, p1, b2, out);
    }
}